// round 11
// baseline (speedup 1.0000x reference)
#include <cuda_runtime.h>
#include <cuda_fp16.h>
#include <cuda_fp8.h>
#include <cstdint>

// Problem shapes (fixed by the dataset)
#define M_FULL  16384
#define N_DIM   4096
#define K_DIM   4096

// Scratch (allocation-free rule: __device__ globals)
__device__ __half g_A16[(size_t)(M_FULL / 2) * K_DIM];  // fp16 Asum [M][K]
__device__ __half g_B16[(size_t)K_DIM * N_DIM];          // fp16 B^T [N][K]

// ---------------------------------------------------------------------------
// fp8 helpers
// ---------------------------------------------------------------------------
__device__ __forceinline__ float fp8_round(float x) {
    __nv_fp8_storage_t s = __nv_cvt_float_to_fp8(x, __NV_SATFINITE, __NV_E4M3);
    __half_raw hr = __nv_cvt_fp8_to_halfraw(s, __NV_E4M3);
    return __half2float(__half(hr));
}
__device__ __forceinline__ __half fp8_to_half(float x) {
    __nv_fp8_storage_t s = __nv_cvt_float_to_fp8(x, __NV_SATFINITE, __NV_E4M3);
    __half_raw hr = __nv_cvt_fp8_to_halfraw(s, __NV_E4M3);  // e4m3 exact in fp16
    return __half(hr);
}

// ---------------------------------------------------------------------------
// Fused prep kernel:
//   part 1 (blocks [0, rblocks)): Asum = sum_w fp8round(A_w), fp32 acc -> fp16
//   part 2 (rest):               W [K][N] f32 -> g_B16 = B^T [N][K] fp16
// ---------------------------------------------------------------------------
__global__ __launch_bounds__(256)
void prep_kernel(const float* __restrict__ A, const float* __restrict__ W,
                 int shard4, int world, int rblocks) {
    if ((int)blockIdx.x < rblocks) {
        int idx = blockIdx.x * 256 + threadIdx.x;
        if (idx >= shard4) return;
        const float4* A4 = (const float4*)A;
        float4 s = make_float4(0.f, 0.f, 0.f, 0.f);
        for (int w = 0; w < world; w++) {
            float4 v = A4[(size_t)w * shard4 + idx];
            s.x += fp8_round(v.x);
            s.y += fp8_round(v.y);
            s.z += fp8_round(v.z);
            s.w += fp8_round(v.w);
        }
        ((__half2*)g_A16)[idx * 2 + 0] = __floats2half2_rn(s.x, s.y);
        ((__half2*)g_A16)[idx * 2 + 1] = __floats2half2_rn(s.z, s.w);
    } else {
        __shared__ float t[32][33];
        int q = blockIdx.x - rblocks;              // 0 .. 128*128-1
        int n0 = (q & 127) * 32;
        int k0 = (q >> 7) * 32;
        int tx = threadIdx.x & 31, ty = threadIdx.x >> 5;   // (32, 8)
#pragma unroll
        for (int i = 0; i < 4; i++)
            t[ty + 8 * i][tx] = W[(size_t)(k0 + ty + 8 * i) * N_DIM + n0 + tx];
        __syncthreads();
#pragma unroll
        for (int i = 0; i < 4; i++)
            g_B16[(size_t)(n0 + ty + 8 * i) * K_DIM + k0 + tx] = fp8_to_half(t[tx][ty + 8 * i]);
    }
}

// ---------------------------------------------------------------------------
// PTX helpers (sm_80-era instructions; valid on compute_103)
// ---------------------------------------------------------------------------
__device__ __forceinline__ uint32_t smem_u32(const void* p) {
    uint32_t a;
    asm("{ .reg .u64 t; cvta.to.shared.u64 t, %1; cvt.u32.u64 %0, t; }" : "=r"(a) : "l"(p));
    return a;
}
__device__ __forceinline__ void ldsm_x4(uint32_t& r0, uint32_t& r1, uint32_t& r2, uint32_t& r3,
                                        uint32_t addr) {
    asm volatile("ldmatrix.sync.aligned.m8n8.x4.shared.b16 {%0,%1,%2,%3}, [%4];"
                 : "=r"(r0), "=r"(r1), "=r"(r2), "=r"(r3) : "r"(addr));
}
__device__ __forceinline__ void mma_16816(float* c, const uint32_t* a, uint32_t b0, uint32_t b1) {
    asm volatile("mma.sync.aligned.m16n8k16.row.col.f32.f16.f16.f32 "
                 "{%0,%1,%2,%3}, {%4,%5,%6,%7}, {%8,%9}, {%0,%1,%2,%3};"
                 : "+f"(c[0]), "+f"(c[1]), "+f"(c[2]), "+f"(c[3])
                 : "r"(a[0]), "r"(a[1]), "r"(a[2]), "r"(a[3]), "r"(b0), "r"(b1));
}
__device__ __forceinline__ void cp16(uint32_t smem, const void* g) {
    asm volatile("cp.async.cg.shared.global [%0], [%1], 16;" :: "r"(smem), "l"(g) : "memory");
}
#define CP_COMMIT() asm volatile("cp.async.commit_group;" ::: "memory")
#define CP_WAIT(n)  asm volatile("cp.async.wait_group %0;" :: "n"(n) : "memory")

// ---------------------------------------------------------------------------
// GEMM: 128x128 CTA tile, 256 threads (8 warps, warp tile 32x64), BK=64,
//       3-stage cp.async, 2 CTAs/SM (register-limited design),
//       fused scale_b + fp16-round epilogue.
// ---------------------------------------------------------------------------
#define BM 128
#define BN 128
#define BKH 64                        // halves per stage chunk (128 B rows)
#define STAGES 3
#define ROWB 128                      // bytes per smem row
#define A_STAGE (BM * ROWB)           // 16 KB
#define B_STAGE (BN * ROWB)           // 16 KB
#define STAGE_BYTES (A_STAGE + B_STAGE)
#define GEMM_SMEM (STAGES * STAGE_BYTES)   // 96 KB -> 2 CTAs/SM (smem side)

__device__ __forceinline__ uint32_t sw_off(int row, int chunk) {
    return (uint32_t)(row * ROWB + ((chunk ^ (row & 7)) << 4));
}

__global__ __launch_bounds__(256, 2)
void gemm_mma_kernel(const float* __restrict__ scale_b, float* __restrict__ out) {
    extern __shared__ char sm[];
    const uint32_t sbase = smem_u32(sm);

    const int tid  = threadIdx.x;
    const int lane = tid & 31;
    const int warp = tid >> 5;        // 0..7
    const int wm   = warp & 3;        // 0..3 -> 32-row group
    const int wn   = warp >> 2;       // 0..1 -> 64-col group
    const int bm = blockIdx.y * BM;
    const int bn = blockIdx.x * BN;

    const __half* Ag = g_A16 + (size_t)bm * K_DIM;
    const __half* Bg = g_B16 + (size_t)bn * K_DIM;

    // cp.async mapping: thread owns chunk (tid&7), base row tid>>3 (0..31)
    const int crow = tid >> 3;
    const int cchk = tid & 7;

    float acc[2][8][4] = {};          // [mi][n8][reg] -> 64 regs

    const int KITER = K_DIM / BKH;    // 64

    // Prologue: fill stages 0..STAGES-2
#pragma unroll
    for (int s = 0; s < STAGES - 1; s++) {
        const __half* ga = Ag + (size_t)s * BKH + cchk * 8;
        const __half* gb = Bg + (size_t)s * BKH + cchk * 8;
        uint32_t as = sbase + s * STAGE_BYTES;
        uint32_t bs = as + A_STAGE;
#pragma unroll
        for (int i = 0; i < 4; i++) {
            int r = crow + i * 32;
            cp16(as + sw_off(r, cchk), ga + (size_t)r * K_DIM);
            cp16(bs + sw_off(r, cchk), gb + (size_t)r * K_DIM);
        }
        CP_COMMIT();
    }

    for (int it = 0; it < KITER; it++) {
        CP_WAIT(STAGES - 2);
        __syncthreads();              // protects the stage about to be reused

        // Issue loads for stage it+STAGES-1 (overlaps with compute below)
        int nk = it + STAGES - 1;
        if (nk < KITER) {
            int s = nk % STAGES;
            const __half* ga = Ag + (size_t)nk * BKH + cchk * 8;
            const __half* gb = Bg + (size_t)nk * BKH + cchk * 8;
            uint32_t as = sbase + s * STAGE_BYTES;
            uint32_t bs = as + A_STAGE;
#pragma unroll
            for (int i = 0; i < 4; i++) {
                int r = crow + i * 32;
                cp16(as + sw_off(r, cchk), ga + (size_t)r * K_DIM);
                cp16(bs + sw_off(r, cchk), gb + (size_t)r * K_DIM);
            }
            CP_COMMIT();
        } else {
            CP_COMMIT();              // keep group count aligned with CP_WAIT
        }

        // Compute on stage it%STAGES
        const uint32_t As = sbase + (it % STAGES) * STAGE_BYTES;
        const uint32_t Bs = As + A_STAGE;
#pragma unroll
        for (int ks = 0; ks < 4; ks++) {
            const int ch = ks * 2 + (lane >> 4);
            uint32_t a[2][4];
#pragma unroll
            for (int mi = 0; mi < 2; mi++) {
                int r = wm * 32 + mi * 16 + (lane & 15);
                ldsm_x4(a[mi][0], a[mi][1], a[mi][2], a[mi][3], As + sw_off(r, ch));
            }
            uint32_t b[4][4];
#pragma unroll
            for (int nj = 0; nj < 4; nj++) {
                int r = wn * 64 + nj * 16 + (lane & 15);
                ldsm_x4(b[nj][0], b[nj][1], b[nj][2], b[nj][3], Bs + sw_off(r, ch));
            }
#pragma unroll
            for (int mi = 0; mi < 2; mi++)
#pragma unroll
                for (int n8 = 0; n8 < 8; n8++) {
                    int nj = n8 >> 1, hi = n8 & 1;
                    mma_16816(acc[mi][n8], a[mi], b[nj][hi], b[nj][hi + 2]);
                }
        }
    }

    // Fused epilogue: scale_b + fp16 quantize, store fp32
#pragma unroll
    for (int mi = 0; mi < 2; mi++) {
#pragma unroll
        for (int n8 = 0; n8 < 8; n8++) {
            const float* c = acc[mi][n8];
            int row = bm + wm * 32 + mi * 16 + (lane >> 2);
            int col = bn + wn * 64 + n8 * 8 + (lane & 3) * 2;
            float2 s0 = *(const float2*)&scale_b[col];
            float2 v0;
            v0.x = __half2float(__float2half(c[0] * s0.x));
            v0.y = __half2float(__float2half(c[1] * s0.y));
            *(float2*)&out[(size_t)row * N_DIM + col] = v0;
            float2 v1;
            v1.x = __half2float(__float2half(c[2] * s0.x));
            v1.y = __half2float(__float2half(c[3] * s0.y));
            *(float2*)&out[(size_t)(row + 8) * N_DIM + col] = v1;
        }
    }
}

// ---------------------------------------------------------------------------
// Host
// ---------------------------------------------------------------------------
extern "C" void kernel_launch(void* const* d_in, const int* in_sizes, int n_in,
                              void* d_out, int out_size) {
    const float* input = nullptr; const float* weight = nullptr; const float* scale_b = nullptr;
    long long input_elems = 0;
    for (int i = 0; i < n_in; i++) {
        long long sz = in_sizes[i];
        if (sz == (long long)K_DIM * N_DIM && !weight)      weight = (const float*)d_in[i];
        else if (sz == N_DIM && !scale_b)                   scale_b = (const float*)d_in[i];
        else if (sz > (long long)K_DIM * N_DIM)             { input = (const float*)d_in[i]; input_elems = sz; }
    }
    float* out = (float*)d_out;   // harness output buffer is FLOAT32

    long long M_full   = input_elems / K_DIM;
    long long out_rows = (long long)out_size / N_DIM;
    int world = (int)(M_full / (out_rows > 0 ? out_rows : M_full));
    if (world < 1) world = 1;
    int M_out = (int)(M_full / world);

    {
        int shard4 = (M_out * K_DIM) / 4;
        int rblocks = (shard4 + 255) / 256;
        int tblocks = (N_DIM / 32) * (K_DIM / 32);
        prep_kernel<<<rblocks + tblocks, 256>>>(input, weight, shard4, world, rblocks);
    }
    {
        cudaFuncSetAttribute(gemm_mma_kernel, cudaFuncAttributeMaxDynamicSharedMemorySize,
                             GEMM_SMEM);
        dim3 grid(N_DIM / BN, M_out / BM);
        gemm_mma_kernel<<<grid, 256, GEMM_SMEM>>>(scale_b, out);
    }
}

// round 12
// speedup vs baseline: 1.0314x; 1.0314x over previous
#include <cuda_runtime.h>
#include <cuda_fp16.h>
#include <cuda_fp8.h>
#include <cstdint>

// Problem shapes (fixed by the dataset)
#define M_FULL  16384
#define N_DIM   4096
#define K_DIM   4096

// Scratch (allocation-free rule: __device__ globals)
__device__ __half g_A16[(size_t)(M_FULL / 2) * K_DIM];  // fp16 Asum [M][K]
__device__ __half g_B16[(size_t)K_DIM * N_DIM];          // fp16 B^T [N][K]

// ---------------------------------------------------------------------------
// fp8 helpers
// ---------------------------------------------------------------------------
__device__ __forceinline__ float fp8_round(float x) {
    __nv_fp8_storage_t s = __nv_cvt_float_to_fp8(x, __NV_SATFINITE, __NV_E4M3);
    __half_raw hr = __nv_cvt_fp8_to_halfraw(s, __NV_E4M3);
    return __half2float(__half(hr));
}
__device__ __forceinline__ __half fp8_to_half(float x) {
    __nv_fp8_storage_t s = __nv_cvt_float_to_fp8(x, __NV_SATFINITE, __NV_E4M3);
    __half_raw hr = __nv_cvt_fp8_to_halfraw(s, __NV_E4M3);  // e4m3 exact in fp16
    return __half(hr);
}

// ---------------------------------------------------------------------------
// Fused prep kernel:
//   part 1 (blocks [0, rblocks)): Asum = sum_w fp8round(A_w), fp32 acc -> fp16
//   part 2 (rest):               W [K][N] f32 -> g_B16 = B^T [N][K] fp16
// ---------------------------------------------------------------------------
__global__ __launch_bounds__(256)
void prep_kernel(const float* __restrict__ A, const float* __restrict__ W,
                 int shard4, int world, int rblocks) {
    if ((int)blockIdx.x < rblocks) {
        int idx = blockIdx.x * 256 + threadIdx.x;
        if (idx >= shard4) return;
        const float4* A4 = (const float4*)A;
        float4 s = make_float4(0.f, 0.f, 0.f, 0.f);
        for (int w = 0; w < world; w++) {
            float4 v = A4[(size_t)w * shard4 + idx];
            s.x += fp8_round(v.x);
            s.y += fp8_round(v.y);
            s.z += fp8_round(v.z);
            s.w += fp8_round(v.w);
        }
        ((__half2*)g_A16)[idx * 2 + 0] = __floats2half2_rn(s.x, s.y);
        ((__half2*)g_A16)[idx * 2 + 1] = __floats2half2_rn(s.z, s.w);
    } else {
        __shared__ float t[32][33];
        int q = blockIdx.x - rblocks;              // 0 .. 128*128-1
        int n0 = (q & 127) * 32;
        int k0 = (q >> 7) * 32;
        int tx = threadIdx.x & 31, ty = threadIdx.x >> 5;   // (32, 8)
#pragma unroll
        for (int i = 0; i < 4; i++)
            t[ty + 8 * i][tx] = W[(size_t)(k0 + ty + 8 * i) * N_DIM + n0 + tx];
        __syncthreads();
#pragma unroll
        for (int i = 0; i < 4; i++)
            g_B16[(size_t)(n0 + ty + 8 * i) * K_DIM + k0 + tx] = fp8_to_half(t[tx][ty + 8 * i]);
    }
}

// ---------------------------------------------------------------------------
// PTX helpers (sm_80-era instructions; valid on compute_103)
// ---------------------------------------------------------------------------
__device__ __forceinline__ uint32_t smem_u32(const void* p) {
    uint32_t a;
    asm("{ .reg .u64 t; cvta.to.shared.u64 t, %1; cvt.u32.u64 %0, t; }" : "=r"(a) : "l"(p));
    return a;
}
__device__ __forceinline__ void ldsm_x4(uint32_t& r0, uint32_t& r1, uint32_t& r2, uint32_t& r3,
                                        uint32_t addr) {
    asm volatile("ldmatrix.sync.aligned.m8n8.x4.shared.b16 {%0,%1,%2,%3}, [%4];"
                 : "=r"(r0), "=r"(r1), "=r"(r2), "=r"(r3) : "r"(addr));
}
__device__ __forceinline__ void mma_16816(float* c, const uint32_t* a, uint32_t b0, uint32_t b1) {
    asm volatile("mma.sync.aligned.m16n8k16.row.col.f32.f16.f16.f32 "
                 "{%0,%1,%2,%3}, {%4,%5,%6,%7}, {%8,%9}, {%0,%1,%2,%3};"
                 : "+f"(c[0]), "+f"(c[1]), "+f"(c[2]), "+f"(c[3])
                 : "r"(a[0]), "r"(a[1]), "r"(a[2]), "r"(a[3]), "r"(b0), "r"(b1));
}
__device__ __forceinline__ void cp16(uint32_t smem, const void* g) {
    asm volatile("cp.async.cg.shared.global [%0], [%1], 16;" :: "r"(smem), "l"(g) : "memory");
}
#define CP_COMMIT() asm volatile("cp.async.commit_group;" ::: "memory")
#define CP_WAIT(n)  asm volatile("cp.async.wait_group %0;" :: "n"(n) : "memory")

// ---------------------------------------------------------------------------
// GEMM: 128x256 CTA tile, 256 threads (8 warps, warp tile 64x64), BK=64,
//       4-stage cp.async ring, REGISTER-DOUBLE-BUFFERED fragments,
//       cp.async spread across ks-steps, fused scale_b + fp16 epilogue.
// ---------------------------------------------------------------------------
#define BM 128
#define BN 256
#define BKH 64                        // halves per stage chunk (128 B rows)
#define STAGES 4
#define ROWB 128                      // bytes per smem row
#define A_STAGE (BM * ROWB)           // 16 KB
#define B_STAGE (BN * ROWB)           // 32 KB
#define STAGE_BYTES (A_STAGE + B_STAGE)
#define GEMM_SMEM (STAGES * STAGE_BYTES)   // 192 KB, 1 CTA/SM

__device__ __forceinline__ uint32_t sw_off(int row, int chunk) {
    return (uint32_t)(row * ROWB + ((chunk ^ (row & 7)) << 4));
}

__global__ __launch_bounds__(256, 1)
void gemm_mma_kernel(const float* __restrict__ scale_b, float* __restrict__ out) {
    extern __shared__ char sm[];
    const uint32_t sbase = smem_u32(sm);

    const int tid  = threadIdx.x;
    const int lane = tid & 31;
    const int warp = tid >> 5;        // 0..7
    const int wm   = warp & 1;        // 0..1 -> 64-row group
    const int wn   = warp >> 1;       // 0..3 -> 64-col group
    const int bm = blockIdx.y * BM;
    const int bn = blockIdx.x * BN;

    const __half* Ag = g_A16 + (size_t)bm * K_DIM;
    const __half* Bg = g_B16 + (size_t)bn * K_DIM;

    // cp.async mapping: thread owns chunk (tid&7), base row tid>>3 (0..31)
    const int crow = tid >> 3;
    const int cchk = tid & 7;

    float acc[4][8][4] = {};          // [mi][n8][reg] -> 128 regs

    const int KITER = K_DIM / BKH;    // 64
    const int arow = wm * 64 + (lane & 15);   // ldsm A row base
    const int brow = wn * 64 + (lane & 15);   // ldsm B row base
    const int chsel = lane >> 4;              // 0/1 within k16 pair

    // Prologue: fill stages 0..STAGES-2
#pragma unroll
    for (int s = 0; s < STAGES - 1; s++) {
        const __half* ga = Ag + (size_t)s * BKH + cchk * 8;
        const __half* gb = Bg + (size_t)s * BKH + cchk * 8;
        uint32_t as = sbase + s * STAGE_BYTES;
        uint32_t bs = as + A_STAGE;
#pragma unroll
        for (int i = 0; i < 4; i++)
            cp16(as + sw_off(crow + i * 32, cchk), ga + (size_t)(crow + i * 32) * K_DIM);
#pragma unroll
        for (int i = 0; i < 8; i++)
            cp16(bs + sw_off(crow + i * 32, cchk), gb + (size_t)(crow + i * 32) * K_DIM);
        CP_COMMIT();
    }

    uint32_t af[2][4][4];             // [buf][mi][reg]
    uint32_t bf[2][4][4];             // [buf][nj][reg]

    for (int it = 0; it < KITER; it++) {
        CP_WAIT(STAGES - 2);
        __syncthreads();              // stage it is ready; stage being refilled is free

        const uint32_t As = sbase + (it % STAGES) * STAGE_BYTES;
        const uint32_t Bs = As + A_STAGE;

        // next-stage cp.async targets (issued spread across ks-steps below)
        const int nk = it + STAGES - 1;
        const bool do_ld = (nk < KITER);
        const __half* ga = Ag + (size_t)nk * BKH + cchk * 8;
        const __half* gb = Bg + (size_t)nk * BKH + cchk * 8;
        const uint32_t nas = sbase + (nk % STAGES) * STAGE_BYTES;
        const uint32_t nbs = nas + A_STAGE;

        // Preload ks=0 fragments into buffer 0
        {
            const int ch = chsel;     // ks=0: ch = 0*2 + chsel
#pragma unroll
            for (int mi = 0; mi < 4; mi++)
                ldsm_x4(af[0][mi][0], af[0][mi][1], af[0][mi][2], af[0][mi][3],
                        As + sw_off(arow + mi * 16, ch));
#pragma unroll
            for (int nj = 0; nj < 4; nj++)
                ldsm_x4(bf[0][nj][0], bf[0][nj][1], bf[0][nj][2], bf[0][nj][3],
                        Bs + sw_off(brow + nj * 16, ch));
        }

#pragma unroll
        for (int ks = 0; ks < 4; ks++) {
            const int cur = ks & 1;
            const int nxt = cur ^ 1;

            // Prefetch ks+1 fragments (hidden under this ks's mma)
            if (ks < 3) {
                const int ch = (ks + 1) * 2 + chsel;
#pragma unroll
                for (int mi = 0; mi < 4; mi++)
                    ldsm_x4(af[nxt][mi][0], af[nxt][mi][1], af[nxt][mi][2], af[nxt][mi][3],
                            As + sw_off(arow + mi * 16, ch));
#pragma unroll
                for (int nj = 0; nj < 4; nj++)
                    ldsm_x4(bf[nxt][nj][0], bf[nxt][nj][1], bf[nxt][nj][2], bf[nxt][nj][3],
                            Bs + sw_off(brow + nj * 16, ch));
            }

            // Spread next-stage cp.async: 3 loads per ks-step (1 A + 2 B)
            if (do_ld) {
                int r = crow + ks * 32;
                cp16(nas + sw_off(r, cchk), ga + (size_t)r * K_DIM);
                int r0 = crow + (ks * 2) * 32;
                int r1 = crow + (ks * 2 + 1) * 32;
                cp16(nbs + sw_off(r0, cchk), gb + (size_t)r0 * K_DIM);
                cp16(nbs + sw_off(r1, cchk), gb + (size_t)r1 * K_DIM);
            }
            if (ks == 3) CP_COMMIT();

            // MMA on current buffer
#pragma unroll
            for (int mi = 0; mi < 4; mi++)
#pragma unroll
                for (int n8 = 0; n8 < 8; n8++) {
                    int nj = n8 >> 1, hi = n8 & 1;
                    mma_16816(acc[mi][n8], af[cur][mi], bf[cur][nj][hi], bf[cur][nj][hi + 2]);
                }
        }
    }

    // Fused epilogue: scale_b + fp16 quantize, store fp32
#pragma unroll
    for (int mi = 0; mi < 4; mi++) {
#pragma unroll
        for (int n8 = 0; n8 < 8; n8++) {
            const float* c = acc[mi][n8];
            int row = bm + wm * 64 + mi * 16 + (lane >> 2);
            int col = bn + wn * 64 + n8 * 8 + (lane & 3) * 2;
            float2 s0 = *(const float2*)&scale_b[col];
            float2 v0;
            v0.x = __half2float(__float2half(c[0] * s0.x));
            v0.y = __half2float(__float2half(c[1] * s0.y));
            *(float2*)&out[(size_t)row * N_DIM + col] = v0;
            float2 v1;
            v1.x = __half2float(__float2half(c[2] * s0.x));
            v1.y = __half2float(__float2half(c[3] * s0.y));
            *(float2*)&out[(size_t)(row + 8) * N_DIM + col] = v1;
        }
    }
}

// ---------------------------------------------------------------------------
// Host
// ---------------------------------------------------------------------------
extern "C" void kernel_launch(void* const* d_in, const int* in_sizes, int n_in,
                              void* d_out, int out_size) {
    const float* input = nullptr; const float* weight = nullptr; const float* scale_b = nullptr;
    long long input_elems = 0;
    for (int i = 0; i < n_in; i++) {
        long long sz = in_sizes[i];
        if (sz == (long long)K_DIM * N_DIM && !weight)      weight = (const float*)d_in[i];
        else if (sz == N_DIM && !scale_b)                   scale_b = (const float*)d_in[i];
        else if (sz > (long long)K_DIM * N_DIM)             { input = (const float*)d_in[i]; input_elems = sz; }
    }
    float* out = (float*)d_out;   // harness output buffer is FLOAT32

    long long M_full   = input_elems / K_DIM;
    long long out_rows = (long long)out_size / N_DIM;
    int world = (int)(M_full / (out_rows > 0 ? out_rows : M_full));
    if (world < 1) world = 1;
    int M_out = (int)(M_full / world);

    {
        int shard4 = (M_out * K_DIM) / 4;
        int rblocks = (shard4 + 255) / 256;
        int tblocks = (N_DIM / 32) * (K_DIM / 32);
        prep_kernel<<<rblocks + tblocks, 256>>>(input, weight, shard4, world, rblocks);
    }
    {
        cudaFuncSetAttribute(gemm_mma_kernel, cudaFuncAttributeMaxDynamicSharedMemorySize,
                             GEMM_SMEM);
        dim3 grid(N_DIM / BN, M_out / BM);
        gemm_mma_kernel<<<grid, 256, GEMM_SMEM>>>(scale_b, out);
    }
}